// round 6
// baseline (speedup 1.0000x reference)
#include <cuda_runtime.h>
#include <math.h>
#include <stdint.h>

// Problem constants (fixed shapes)
#define NB_   4096        // B*N
#define KK_   48
#define HH_   128
#define FF_   512
#define CHUNK_ 32         // k-rows per streamed weight chunk
__device__ __constant__ float kINV_SCALE = 1.0f/30.0f;
#define EPS_  1e-5f

#define THREADS_E 192

// Scratch (device globals; no allocation allowed)
__device__ float g_P[NB_*HH_];
__device__ float g_Q[NB_*HH_];
__device__ float g_hV1[NB_*HH_];
__device__ float g_hV2[NB_*HH_];

// ---------------- helpers ----------------
__device__ __forceinline__ float gelu_f(float x){
    return 0.5f*x*(1.0f + erff(x*0.70710678118654752f));
}

__device__ __forceinline__ unsigned long long pack2(float lo, float hi){
    unsigned long long r;
    asm("mov.b64 %0, {%1,%2};" : "=l"(r) : "r"(__float_as_uint(lo)), "r"(__float_as_uint(hi)));
    return r;
}
__device__ __forceinline__ void unpack2(unsigned long long v, float& lo, float& hi){
    unsigned ulo, uhi;
    asm("mov.b64 {%0,%1}, %2;" : "=r"(ulo), "=r"(uhi) : "l"(v));
    lo = __uint_as_float(ulo); hi = __uint_as_float(uhi);
}
__device__ __forceinline__ unsigned long long fma2(unsigned long long a,
                                                   unsigned long long b,
                                                   unsigned long long c){
    unsigned long long d;
    asm("fma.rn.f32x2 %0, %1, %2, %3;" : "=l"(d) : "l"(a), "l"(b), "l"(c));
    return d;
}

__device__ __forceinline__ void cp_async16(void* sdst, const void* gsrc){
    unsigned sa = (unsigned)__cvta_generic_to_shared(sdst);
    asm volatile("cp.async.cg.shared.global [%0], [%1], 16;" :: "r"(sa), "l"(gsrc));
}
#define CP_COMMIT() asm volatile("cp.async.commit_group;")
#define CP_WAIT(n)  asm volatile("cp.async.wait_group %0;" :: "n"(n))

// ---------------- kernel 1: per-node P/Q precompute ----------------
// 256 threads: half 0 computes P = h_V@W[0:128]+b, half 1 computes Q = h_V@W[256:384].
__global__ void __launch_bounds__(256) prep_pq_kernel(
    const float* __restrict__ hV, const float* __restrict__ W,
    const float* __restrict__ b,  float* __restrict__ P, float* __restrict__ Q)
{
    __shared__ float sh[8][HH_];
    int tid = threadIdx.x;
    int nb = blockIdx.x * 8;
    for (int idx = tid; idx < 8*HH_; idx += 256)
        sh[idx>>7][idx&127] = hV[nb*HH_ + idx];
    __syncthreads();
    int j   = tid & 127;
    int sel = tid >> 7;
    const float* Wblk = W + (sel ? 256*HH_ : 0);
    float acc[8];
    #pragma unroll
    for (int r=0;r<8;r++) acc[r]=0.f;
    #pragma unroll 4
    for (int i=0;i<HH_;i++){
        float w = Wblk[i*HH_ + j];
        #pragma unroll
        for (int r=0;r<8;r++)
            acc[r] = fmaf(sh[r][i], w, acc[r]);
    }
    if (sel == 0){
        float bb = b[j];
        #pragma unroll
        for (int r=0;r<8;r++) P[(nb+r)*HH_ + j] = acc[r] + bb;
    } else {
        #pragma unroll
        for (int r=0;r<8;r++) Q[(nb+r)*HH_ + j] = acc[r];
    }
}

// ---------------- fused edge-chain kernel ----------------
// Activation buffers are TRANSPOSED pair-layout: value(r, c) lives at
// float index c*XS2 + r, i.e. column c holds 48 consecutive floats (24 pairs).
#define XS2 52   // floats per transposed column (48 + pad; even, mult of 4)

// smem layout (floats)
#define OFF_WC   0                       // 2 chunk buffers: 2*CHUNK_*HH_ = 8192
#define OFF_A    8192                    // buffer A: 128*52 = 6656
#define OFF_B    (OFF_A + HH_*XS2)       // 14848: buffer B (Obt / ping-pong)
#define OFF_MASK (OFF_B + HH_*XS2)       // 21504
#define OFF_IDX  (OFF_MASK + KK_)        // 21552
#define OFF_RED  (OFF_IDX + KK_)         // 21600
#define SMEM_FLOATS (OFF_RED + 16)       // 21616
#define EDGE_SMEM_BYTES (SMEM_FLOATS*4)  // 86464 B -> 2 CTAs/SM

__device__ __forceinline__ void load_chunk(float* dst, const float* src, int tid){
    // CHUNK_*HH_ = 4096 floats = 1024 x 16B
    for (int i = tid; i < CHUNK_*HH_/4; i += THREADS_E)
        cp_async16(dst + i*4, src + i*4);
    CP_COMMIT();
}

// 48x128 @ 128x128 tile GEMM; 192 threads; 8-row x 4-col thread tile; f32x2.
// Xs: input in transposed pair layout. Ys: output written transposed.
// mode 0: acc init from ObT (same layout; includes bias), gelu.
// mode 1: acc init from bias4, gelu.  mode 2: acc init from bias4, no gelu.
// cp.async contract: entry = chunk0 of Wg committed as SOLE outstanding group;
// exit = zero outstanding groups. Ys visible to other threads only after the
// next __syncthreads() executed by all (the next gemm's first internal sync,
// or an explicit one).
__device__ __forceinline__ void gemm8(const float* __restrict__ Xs,
    const float* __restrict__ Wg, float* __restrict__ Wc, float* __restrict__ Ys,
    const float* __restrict__ ObT, float4 bias, int mode, int tid)
{
    int cg = tid & 31, rg = tid >> 5;   // rg 0..5
    int c0 = cg*4;
    int r0 = rg*8;                      // 8 rows -> 4 pairs
    unsigned long long acc[4][4];       // [pair i][col j]
    if (mode == 0){
        #pragma unroll
        for (int j=0;j<4;j++)
            #pragma unroll
            for (int i=0;i<4;i++)
                acc[i][j] = *reinterpret_cast<const unsigned long long*>(
                    ObT + (c0+j)*XS2 + r0 + 2*i);
    } else {
        unsigned long long bb0 = pack2(bias.x, bias.x);
        unsigned long long bb1 = pack2(bias.y, bias.y);
        unsigned long long bb2 = pack2(bias.z, bias.z);
        unsigned long long bb3 = pack2(bias.w, bias.w);
        #pragma unroll
        for (int i=0;i<4;i++){ acc[i][0]=bb0; acc[i][1]=bb1; acc[i][2]=bb2; acc[i][3]=bb3; }
    }

    #pragma unroll
    for (int c = 0; c < HH_/CHUNK_; c++){
        if (c < HH_/CHUNK_ - 1){
            load_chunk(Wc + ((c+1)&1)*CHUNK_*HH_, Wg + (c+1)*CHUNK_*HH_, tid);
            CP_WAIT(1);                 // chunk c arrived (this thread)
        } else {
            CP_WAIT(0);
        }
        __syncthreads();                // chunk c visible; prev buffer reads done
        const float* Wsb = Wc + (c&1)*CHUNK_*HH_;
        const float* Xrow = Xs + c*CHUNK_*XS2 + r0;
        #pragma unroll 4
        for (int kk2 = 0; kk2 < CHUNK_; kk2++){
            float4 w = *reinterpret_cast<const float4*>(Wsb + kk2*HH_ + c0);
            unsigned long long wd0 = pack2(w.x, w.x);
            unsigned long long wd1 = pack2(w.y, w.y);
            unsigned long long wd2 = pack2(w.z, w.z);
            unsigned long long wd3 = pack2(w.w, w.w);
            const float* xr = Xrow + kk2*XS2;
            ulonglong2 xa = *reinterpret_cast<const ulonglong2*>(xr);      // pairs r0..r0+3
            ulonglong2 xb = *reinterpret_cast<const ulonglong2*>(xr + 4);  // pairs r0+4..r0+7
            unsigned long long xp0 = xa.x, xp1 = xa.y, xp2 = xb.x, xp3 = xb.y;
            acc[0][0]=fma2(xp0,wd0,acc[0][0]); acc[0][1]=fma2(xp0,wd1,acc[0][1]);
            acc[0][2]=fma2(xp0,wd2,acc[0][2]); acc[0][3]=fma2(xp0,wd3,acc[0][3]);
            acc[1][0]=fma2(xp1,wd0,acc[1][0]); acc[1][1]=fma2(xp1,wd1,acc[1][1]);
            acc[1][2]=fma2(xp1,wd2,acc[1][2]); acc[1][3]=fma2(xp1,wd3,acc[1][3]);
            acc[2][0]=fma2(xp2,wd0,acc[2][0]); acc[2][1]=fma2(xp2,wd1,acc[2][1]);
            acc[2][2]=fma2(xp2,wd2,acc[2][2]); acc[2][3]=fma2(xp2,wd3,acc[2][3]);
            acc[3][0]=fma2(xp3,wd0,acc[3][0]); acc[3][1]=fma2(xp3,wd1,acc[3][1]);
            acc[3][2]=fma2(xp3,wd2,acc[3][2]); acc[3][3]=fma2(xp3,wd3,acc[3][3]);
        }
        __syncthreads();                // all reads of Wc[c&1] done before reuse
    }

    // epilogue: transposed pair stores (STS.64), stride 26 superbanks -> 2-way
    #pragma unroll
    for (int i=0;i<4;i++){
        #pragma unroll
        for (int j=0;j<4;j++){
            float lo, hi; unpack2(acc[i][j], lo, hi);
            if (mode <= 1){ lo = gelu_f(lo); hi = gelu_f(hi); }
            *reinterpret_cast<unsigned long long*>(Ys + (c0+j)*XS2 + r0 + 2*i) = pack2(lo, hi);
        }
    }
}

template<bool NODE>
__global__ void __launch_bounds__(THREADS_E, 2) edge_chain_kernel(
    const float* __restrict__ hE,
    const int*   __restrict__ Eidx,
    const float* __restrict__ maskA,   // NODE only
    const float* __restrict__ P,
    const float* __restrict__ Q,
    const float* __restrict__ Wb,      // middle 128x128 block of the 3H weight
    const float* __restrict__ W2,
    const float* __restrict__ b2,
    const float* __restrict__ W3,
    const float* __restrict__ b3,
    const float* __restrict__ resid,   // NODE: h_V for residual
    const float* __restrict__ g,
    const float* __restrict__ be,
    float* __restrict__ out)           // NODE: hV1[NB*H] ; else d_out edge section
{
    extern __shared__ float sm[];
    float* Wc    = sm + OFF_WC;
    float* A     = sm + OFF_A;
    float* B     = sm + OFF_B;
    float* smask = sm + OFF_MASK;
    int*   sidx  = (int*)(sm + OFF_IDX);
    float* sred  = sm + OFF_RED;

    int tid = threadIdx.x;
    int n = blockIdx.x;            // node index 0..4095
    int bb = n >> 11;              // batch (N = 2048)
    int ebase = n * (KK_*HH_);

    // prefetch chunk0 of W_mid first (overlaps tile prep)
    load_chunk(Wc, Wb, tid);

    if (tid < KK_){
        sidx[tid] = (bb << 11) + Eidx[n*KK_ + tid];
        if (NODE) smask[tid] = maskA[n*KK_ + tid];
    }
    // h_E tile -> A (transposed): A[j*XS2 + r] = hE[r][j]
    for (int idx = tid; idx < KK_*HH_; idx += THREADS_E){
        int r = idx >> 7, j = idx & 127;
        A[j*XS2 + r] = hE[ebase + idx];
    }
    __syncthreads();   // sidx visible
    // Obt -> B (transposed): B[j*XS2 + r] = Pn[j] + Q[neighbor(r)][j]
    const float* Pn = P + n*HH_;
    for (int idx = tid; idx < KK_*HH_; idx += THREADS_E){
        int r = idx >> 7, j = idx & 127;
        B[j*XS2 + r] = Pn[j] + Q[sidx[r]*HH_ + j];
    }
    __syncthreads();   // B (Obt) visible for acc init

    float4 bias2 = *reinterpret_cast<const float4*>(b2 + (tid & 31)*4);
    float4 bias3 = *reinterpret_cast<const float4*>(b3 + (tid & 31)*4);

    gemm8(A, Wb, Wc, B, B, bias2, 0, tid);        // GEMM1: reads A, init Obt, writes B, gelu
    load_chunk(Wc, W2, tid);                      // chunk0 of W2
    gemm8(B, W2, Wc, A, nullptr, bias2, 1, tid);  // GEMM2: +b2, gelu
    load_chunk(Wc, W3, tid);                      // chunk0 of W3
    gemm8(A, W3, Wc, B, nullptr, bias3, 2, tid);  // GEMM3: +b3
    __syncthreads();   // B epilogue visible to all

    if (NODE){
        // masked sum over K, /SCALE, residual, LayerNorm over H (per node)
        float val = 0.f;
        if (tid < HH_){
            const float2* col = reinterpret_cast<const float2*>(B + tid*XS2);
            float s = 0.f;
            #pragma unroll 6
            for (int rp=0; rp<KK_/2; rp++){
                float2 p = col[rp];
                s += smask[2*rp]*p.x + smask[2*rp+1]*p.y;
            }
            val = resid[n*HH_ + tid] + s*kINV_SCALE;
        }
        float s1 = val, s2 = val*val;
        #pragma unroll
        for (int d=16; d>0; d>>=1){
            s1 += __shfl_xor_sync(0xffffffffu, s1, d);
            s2 += __shfl_xor_sync(0xffffffffu, s2, d);
        }
        if (tid < HH_ && (tid & 31)==0){ sred[tid>>5] = s1; sred[4 + (tid>>5)] = s2; }
        __syncthreads();
        if (tid < HH_){
            float t1 = sred[0]+sred[1]+sred[2]+sred[3];
            float t2 = sred[4]+sred[5]+sred[6]+sred[7];
            float m  = t1 * (1.f/128.f);
            float var= t2 * (1.f/128.f) - m*m;
            float rs = rsqrtf(var + EPS_);
            out[n*HH_ + tid] = (val - m)*rs*g[tid] + be[tid];
        }
    } else {
        // per-edge-row LayerNorm of (h_E + msg); 48 rows x 4 threads
        int r = tid >> 2, s = tid & 3;
        int rowg = ebase + r*HH_;
        float v[32];
        float s1=0.f, s2=0.f;
        #pragma unroll
        for (int t=0;t<32;t++){
            int j = s + t*4;
            float x = hE[rowg + j] + B[j*XS2 + r];
            v[t] = x; s1 += x; s2 += x*x;
        }
        #pragma unroll
        for (int d=2; d>0; d>>=1){  // reduce within 4-lane groups
            s1 += __shfl_xor_sync(0xffffffffu, s1, d);
            s2 += __shfl_xor_sync(0xffffffffu, s2, d);
        }
        float m  = s1*(1.f/128.f);
        float var= s2*(1.f/128.f) - m*m;
        float rs = rsqrtf(var + EPS_);
        #pragma unroll
        for (int t=0;t<32;t++){
            int j = s + t*4;
            out[rowg + j] = (v[t]-m)*rs*g[j] + be[j];
        }
    }
}

// ---------------- FFN + LN2 + mask_V (8 nodes per CTA) ----------------
__global__ void __launch_bounds__(256) ffn_kernel(
    const float* __restrict__ hV1,
    const float* __restrict__ Wi, const float* __restrict__ bi,
    const float* __restrict__ Wo, const float* __restrict__ bo,
    const float* __restrict__ g2, const float* __restrict__ be2,
    const float* __restrict__ maskV,
    float* __restrict__ hV2, float* __restrict__ outV)
{
    __shared__ float sh[8][HH_];
    __shared__ float st[8][FF_ + 4];
    __shared__ float sp[2][8][HH_];
    int tid = threadIdx.x;
    int nb = blockIdx.x * 8;
    for (int idx = tid; idx < 8*HH_; idx += 256)
        sh[idx>>7][idx&127] = hV1[nb*HH_ + idx];
    __syncthreads();
    // stage 1: t = gelu(h @ Wi + bi)
    for (int p = 0; p < 2; p++){
        int jj = p*256 + tid;
        float acc[8];
        float b0 = bi[jj];
        #pragma unroll
        for (int r=0;r<8;r++) acc[r] = b0;
        for (int i=0;i<HH_;i+=4){
            float w0 = Wi[(i+0)*FF_ + jj];
            float w1 = Wi[(i+1)*FF_ + jj];
            float w2 = Wi[(i+2)*FF_ + jj];
            float w3 = Wi[(i+3)*FF_ + jj];
            #pragma unroll
            for (int r=0;r<8;r++){
                float4 h4 = *reinterpret_cast<const float4*>(&sh[r][i]);
                acc[r] = fmaf(h4.x,w0, fmaf(h4.y,w1, fmaf(h4.z,w2, fmaf(h4.w,w3, acc[r]))));
            }
        }
        #pragma unroll
        for (int r=0;r<8;r++) st[r][jj] = gelu_f(acc[r]);
    }
    __syncthreads();
    // stage 2: dh = t @ Wo (split i-range across 2 halves)
    {
        int o = tid & 127, half = tid >> 7;
        float acc[8];
        #pragma unroll
        for (int r=0;r<8;r++) acc[r]=0.f;
        int i0 = half*256;
        for (int i=i0; i<i0+256; i+=4){
            float w0 = Wo[(i+0)*HH_ + o];
            float w1 = Wo[(i+1)*HH_ + o];
            float w2 = Wo[(i+2)*HH_ + o];
            float w3 = Wo[(i+3)*HH_ + o];
            #pragma unroll
            for (int r=0;r<8;r++){
                float4 t4 = *reinterpret_cast<const float4*>(&st[r][i]);
                acc[r] = fmaf(t4.x,w0, fmaf(t4.y,w1, fmaf(t4.z,w2, fmaf(t4.w,w3, acc[r]))));
            }
        }
        #pragma unroll
        for (int r=0;r<8;r++) sp[half][r][o] = acc[r];
    }
    __syncthreads();
    // LN over H per row; one warp per row
    int r = tid >> 5, lane = tid & 31;
    float v[4]; float s1=0.f, s2=0.f;
    #pragma unroll
    for (int q=0;q<4;q++){
        int oo = lane*4 + q;
        float x = sh[r][oo] + sp[0][r][oo] + sp[1][r][oo] + bo[oo];
        v[q]=x; s1+=x; s2+=x*x;
    }
    #pragma unroll
    for (int d=16; d>0; d>>=1){
        s1 += __shfl_xor_sync(0xffffffffu, s1, d);
        s2 += __shfl_xor_sync(0xffffffffu, s2, d);
    }
    float m  = s1*(1.f/128.f);
    float var= s2*(1.f/128.f) - m*m;
    float rs = rsqrtf(var + EPS_);
    float mv = maskV[nb + r];
    #pragma unroll
    for (int q=0;q<4;q++){
        int oo = lane*4 + q;
        float o1 = ((v[q]-m)*rs*g2[oo] + be2[oo]) * mv;
        hV2 [(nb+r)*HH_ + oo] = o1;
        outV[(nb+r)*HH_ + oo] = o1;
    }
}

// ---------------- launch ----------------
extern "C" void kernel_launch(void* const* d_in, const int* in_sizes, int n_in,
                              void* d_out, int out_size)
{
    (void)in_sizes; (void)n_in; (void)out_size;
    const float* hV    = (const float*)d_in[0];
    const float* hE    = (const float*)d_in[1];
    const int*   Eidx  = (const int*)  d_in[2];
    const float* maskV = (const float*)d_in[3];
    const float* maskA = (const float*)d_in[4];
    const float* W1  = (const float*)d_in[5];
    const float* b1  = (const float*)d_in[6];
    const float* W2  = (const float*)d_in[7];
    const float* b2  = (const float*)d_in[8];
    const float* W3  = (const float*)d_in[9];
    const float* b3  = (const float*)d_in[10];
    const float* W11 = (const float*)d_in[11];
    const float* b11 = (const float*)d_in[12];
    const float* W12 = (const float*)d_in[13];
    const float* b12 = (const float*)d_in[14];
    const float* W13 = (const float*)d_in[15];
    const float* b13 = (const float*)d_in[16];
    const float* Wi  = (const float*)d_in[17];
    const float* bi  = (const float*)d_in[18];
    const float* Wo  = (const float*)d_in[19];
    const float* bo  = (const float*)d_in[20];
    const float* g1  = (const float*)d_in[21];
    const float* be1 = (const float*)d_in[22];
    const float* g2  = (const float*)d_in[23];
    const float* be2 = (const float*)d_in[24];
    const float* g3  = (const float*)d_in[25];
    const float* be3 = (const float*)d_in[26];

    float* outV = (float*)d_out;
    float* outE = outV + (size_t)NB_*HH_;

    float *P, *Q, *hV1, *hV2;
    cudaGetSymbolAddress((void**)&P,   g_P);
    cudaGetSymbolAddress((void**)&Q,   g_Q);
    cudaGetSymbolAddress((void**)&hV1, g_hV1);
    cudaGetSymbolAddress((void**)&hV2, g_hV2);

    cudaFuncSetAttribute(edge_chain_kernel<true>,
                         cudaFuncAttributeMaxDynamicSharedMemorySize, EDGE_SMEM_BYTES);
    cudaFuncSetAttribute(edge_chain_kernel<false>,
                         cudaFuncAttributeMaxDynamicSharedMemorySize, EDGE_SMEM_BYTES);

    // --- node update ---
    prep_pq_kernel<<<NB_/8, 256>>>(hV, W1, b1, P, Q);
    edge_chain_kernel<true><<<NB_, THREADS_E, EDGE_SMEM_BYTES>>>(
        hE, Eidx, maskA, P, Q, W1 + HH_*HH_, W2, b2, W3, b3, hV, g1, be1, hV1);
    ffn_kernel<<<NB_/8, 256>>>(hV1, Wi, bi, Wo, bo, g2, be2, maskV, hV2, outV);
    // --- edge update ---
    prep_pq_kernel<<<NB_/8, 256>>>(hV2, W11, b11, P, Q);
    edge_chain_kernel<false><<<NB_, THREADS_E, EDGE_SMEM_BYTES>>>(
        hE, Eidx, nullptr, P, Q, W11 + HH_*HH_, W12, b12, W13, b13, nullptr, g3, be3, outE);
}

// round 10
// speedup vs baseline: 1.1474x; 1.1474x over previous
#include <cuda_runtime.h>
#include <cuda_bf16.h>
#include <math.h>
#include <stdint.h>

// Problem constants (fixed shapes)
#define NB_   4096        // B*N
#define KK_   48
#define HH_   128
#define FF_   512
__device__ __constant__ float kINV_SCALE = 1.0f/30.0f;
#define EPS_  1e-5f

#define XST 136           // bf16 row stride for X and W tiles (128 + 8 pad)
#define OST 132           // fp32 row stride for O buffer
#define IMG_ 34816        // bf16 elems per weight image (hi 17408 | lo 17408)

// Scratch (device globals; no allocation allowed)
__device__ float g_P[NB_*HH_];
__device__ float g_Q[NB_*HH_];
__device__ float g_hV1[NB_*HH_];
__device__ float g_hV2[NB_*HH_];
// Pre-split/transposed bf16 weight images, smem-layout-identical: 6 x IMG_
__device__ __align__(16) __nv_bfloat16 g_WTC[6*IMG_];

// ---------------- helpers ----------------
__device__ __forceinline__ float gelu_f(float x){
    return 0.5f*x*(1.0f + erff(x*0.70710678118654752f));
}
__device__ __forceinline__ uint32_t smem_u32(const void* p){
    uint32_t a;
    asm("{ .reg .u64 t; cvta.to.shared.u64 t, %1; cvt.u32.u64 %0, t; }" : "=r"(a) : "l"(p));
    return a;
}
__device__ __forceinline__ void cp_async16(void* sdst, const void* gsrc){
    unsigned sa = (unsigned)__cvta_generic_to_shared(sdst);
    asm volatile("cp.async.cg.shared.global [%0], [%1], 16;" :: "r"(sa), "l"(gsrc));
}
#define CP_COMMIT() asm volatile("cp.async.commit_group;")
#define CP_WAIT(n)  asm volatile("cp.async.wait_group %0;" :: "n"(n))

__device__ __forceinline__ void bsplit(float v, __nv_bfloat16& h, __nv_bfloat16& l){
    h = __float2bfloat16(v);
    l = __float2bfloat16(v - __bfloat162float(h));
}
__device__ __forceinline__ uint32_t pk2(__nv_bfloat16 a, __nv_bfloat16 b){
    uint16_t ua = *(uint16_t*)&a, ub = *(uint16_t*)&b;
    return (uint32_t)ua | ((uint32_t)ub << 16);
}

__device__ __forceinline__ void ldsm_x4(uint32_t& r0, uint32_t& r1, uint32_t& r2, uint32_t& r3,
                                        uint32_t addr){
    asm volatile("ldmatrix.sync.aligned.m8n8.x4.shared.b16 {%0,%1,%2,%3}, [%4];"
        : "=r"(r0), "=r"(r1), "=r"(r2), "=r"(r3) : "r"(addr));
}
__device__ __forceinline__ void mma_bf16(float* d,
    uint32_t a0, uint32_t a1, uint32_t a2, uint32_t a3, uint32_t b0, uint32_t b1){
    asm volatile(
        "mma.sync.aligned.m16n8k16.row.col.f32.bf16.bf16.f32 "
        "{%0,%1,%2,%3}, {%4,%5,%6,%7}, {%8,%9}, {%0,%1,%2,%3};"
        : "+f"(d[0]), "+f"(d[1]), "+f"(d[2]), "+f"(d[3])
        : "r"(a0), "r"(a1), "r"(a2), "r"(a3), "r"(b0), "r"(b1));
}

// ---------------- weight image prep: img[n][k] = W[k][n], bf16 hi/lo split ----------------
__global__ void __launch_bounds__(256) wt_prep_kernel(
    const float* __restrict__ W, __nv_bfloat16* __restrict__ dst)
{
    int idx = blockIdx.x*256 + threadIdx.x;   // grid 64 -> 16384
    int n = idx & 127, k = idx >> 7;
    float w = W[k*HH_ + n];
    __nv_bfloat16 h, l; bsplit(w, h, l);
    dst[n*XST + k] = h;
    dst[17408 + n*XST + k] = l;
}

// ---------------- per-node P/Q precompute (fp32, validated) ----------------
__global__ void __launch_bounds__(256) prep_pq_kernel(
    const float* __restrict__ hV, const float* __restrict__ W,
    const float* __restrict__ b,  float* __restrict__ P, float* __restrict__ Q)
{
    __shared__ float sh[8][HH_];
    int tid = threadIdx.x;
    int nb = blockIdx.x * 8;
    for (int idx = tid; idx < 8*HH_; idx += 256)
        sh[idx>>7][idx&127] = hV[nb*HH_ + idx];
    __syncthreads();
    int j   = tid & 127;
    int sel = tid >> 7;
    const float* Wblk = W + (sel ? 256*HH_ : 0);
    float acc[8];
    #pragma unroll
    for (int r=0;r<8;r++) acc[r]=0.f;
    #pragma unroll 4
    for (int i=0;i<HH_;i++){
        float w = Wblk[i*HH_ + j];
        #pragma unroll
        for (int r=0;r<8;r++)
            acc[r] = fmaf(sh[r][i], w, acc[r]);
    }
    if (sel == 0){
        float bb = b[j];
        #pragma unroll
        for (int r=0;r<8;r++) P[(nb+r)*HH_ + j] = acc[r] + bb;
    } else {
        #pragma unroll
        for (int r=0;r<8;r++) Q[(nb+r)*HH_ + j] = acc[r];
    }
}

// ---------------- fused HMMA edge-chain kernel ----------------
// 2 nodes/CTA, 384 threads = 12 warps; warp tile m16 x n64 (6 x 2 grid).
// smem byte offsets:
#define OFF_XH   0                  // X hi  bf16 [96][136] = 26112 B
#define OFF_XL   26112              // X lo
#define OFF_WH   52224              // W hi  bf16 [128][136] = 34816 B
#define OFF_WL   87040              // W lo  (contiguous after WH)
#define OFF_O    121856             // O fp32 [96][132] = 50688 B
#define OFF_SIDX 172544             // 96 ints
#define OFF_SMASK 172928            // 96 floats
#define OFF_SRED 173312             // 16 floats
#define SMEM_BYTES 173440

template<bool NODE>
__global__ void __launch_bounds__(384, 1) edge_mma_kernel(
    const float* __restrict__ hE, const int* __restrict__ Eidx,
    const float* __restrict__ maskA,
    const float* __restrict__ P, const float* __restrict__ Qm,
    const __nv_bfloat16* __restrict__ WTC,   // 3 images x IMG_ for this phase
    const float* __restrict__ b2v, const float* __restrict__ b3v,
    const float* __restrict__ resid,
    const float* __restrict__ g, const float* __restrict__ be,
    float* __restrict__ out)
{
    extern __shared__ __align__(16) char smraw[];
    uint32_t smb = smem_u32(smraw);
    int tid = threadIdx.x, wid = tid>>5, lane = tid&31;
    int n0 = blockIdx.x*2;

    int mt = wid % 6, nt = wid / 6;
    int m0 = mt*16, nb0 = nt*64;

    float* O = (float*)(smraw + OFF_O);
    int*   sidx = (int*)(smraw + OFF_SIDX);
    float* smask = (float*)(smraw + OFF_SMASK);
    float* sred = (float*)(smraw + OFF_SRED);
    char* xhc = smraw + OFF_XH;
    char* xlc = smraw + OFF_XL;

    // 1. kick cp.async of W(gemm1) hi+lo image (69632 B = 4352 x 16)
    {
        const char* src = (const char*)WTC;
        char* dst = smraw + OFF_WH;
        for (int i = tid; i < 4352; i += 384) cp_async16(dst + i*16, src + i*16);
        CP_COMMIT();
    }
    // 2. gather indices + mask
    if (tid < 96){
        int r = tid;
        int nd = n0 + (r >= KK_);
        int rr = r - (r >= KK_ ? KK_ : 0);
        sidx[r] = ((nd >> 11) << 11) + Eidx[nd*KK_ + rr];
        if (NODE) smask[r] = maskA[nd*KK_ + rr];
    }
    // 3. X = h_E -> bf16 hi/lo tiles (row-major, stride 136)
    for (int idx = tid; idx < 96*HH_; idx += 384){
        int r = idx >> 7, j = idx & 127;
        int nd = n0 + r/KK_, rr = r % KK_;
        float x = hE[((size_t)nd*KK_ + rr)*HH_ + j];
        __nv_bfloat16 h, l; bsplit(x, h, l);
        ((__nv_bfloat16*)xhc)[r*XST + j] = h;
        ((__nv_bfloat16*)xlc)[r*XST + j] = l;
    }
    __syncthreads();           // sidx visible
    // 5. O tile: P[node] + Q[gathered]
    for (int idx = tid; idx < 96*HH_; idx += 384){
        int r = idx >> 7, j = idx & 127;
        int nd = n0 + r/KK_;
        O[r*OST + j] = P[(size_t)nd*HH_ + j] + Qm[(size_t)sidx[r]*HH_ + j];
    }
    CP_WAIT(0);
    __syncthreads();           // X, O, W(g1) all visible

    // fragment address bases (bytes within tiles)
    uint32_t aoff = (uint32_t)((m0 + (lane & 15))*XST + ((lane >> 4) << 3)) * 2;
    uint32_t boff = (uint32_t)((nb0 + (lane & 7) + ((lane >> 4) << 3))*XST
                               + (((lane >> 3) & 1) << 3)) * 2;
    uint32_t xh = smb + OFF_XH, xl = smb + OFF_XL;
    uint32_t wh = smb + OFF_WH, wl = smb + OFF_WL;

    float d[8][4];

    #pragma unroll
    for (int stage = 0; stage < 3; stage++){
        // zero accumulators
        #pragma unroll
        for (int t = 0; t < 8; t++){
            d[t][0]=0.f; d[t][1]=0.f; d[t][2]=0.f; d[t][3]=0.f;
        }
        // mainloop
        #pragma unroll
        for (int k0 = 0; k0 < HH_; k0 += 16){
            uint32_t ah0,ah1,ah2,ah3, al0,al1,al2,al3;
            ldsm_x4(ah0,ah1,ah2,ah3, xh + aoff + k0*2);
            ldsm_x4(al0,al1,al2,al3, xl + aoff + k0*2);
            #pragma unroll
            for (int i = 0; i < 4; i++){
                uint32_t bh0,bh1,bh2,bh3, bl0,bl1,bl2,bl3;
                uint32_t bstep = boff + (uint32_t)(i*16*XST)*2 + k0*2;
                ldsm_x4(bh0,bh1,bh2,bh3, wh + bstep);
                ldsm_x4(bl0,bl1,bl2,bl3, wl + bstep);
                mma_bf16(d[2*i],   ah0,ah1,ah2,ah3, bh0,bh1);
                mma_bf16(d[2*i+1], ah0,ah1,ah2,ah3, bh2,bh3);
                mma_bf16(d[2*i],   ah0,ah1,ah2,ah3, bl0,bl1);
                mma_bf16(d[2*i+1], ah0,ah1,ah2,ah3, bl2,bl3);
                mma_bf16(d[2*i],   al0,al1,al2,al3, bh0,bh1);
                mma_bf16(d[2*i+1], al0,al1,al2,al3, bh2,bh3);
            }
        }
        __syncthreads();       // all X/W reads complete

        if (stage < 2){
            // prefetch next W image
            const char* src = (const char*)(WTC + (size_t)(stage+1)*IMG_);
            char* dst = smraw + OFF_WH;
            for (int i = tid; i < 4352; i += 384) cp_async16(dst + i*16, src + i*16);
            CP_COMMIT();
        }

        // epilogue
        int r0e = m0 + (lane >> 2);
        if (stage == 2){
            // raw D -> O (bias handled downstream)
            #pragma unroll
            for (int t = 0; t < 8; t++){
                int j = nb0 + t*8 + (lane & 3)*2;
                O[r0e*OST + j]     = d[t][0];
                O[r0e*OST + j+1]   = d[t][1];
                O[(r0e+8)*OST + j]   = d[t][2];
                O[(r0e+8)*OST + j+1] = d[t][3];
            }
        } else {
            #pragma unroll
            for (int t = 0; t < 8; t++){
                int j = nb0 + t*8 + (lane & 3)*2;
                float v0, v1, v2, v3;
                if (stage == 0){
                    v0 = gelu_f(d[t][0] + O[r0e*OST + j]);
                    v1 = gelu_f(d[t][1] + O[r0e*OST + j+1]);
                    v2 = gelu_f(d[t][2] + O[(r0e+8)*OST + j]);
                    v3 = gelu_f(d[t][3] + O[(r0e+8)*OST + j+1]);
                } else {
                    float bj0 = b2v[j], bj1 = b2v[j+1];
                    v0 = gelu_f(d[t][0] + bj0);
                    v1 = gelu_f(d[t][1] + bj1);
                    v2 = gelu_f(d[t][2] + bj0);
                    v3 = gelu_f(d[t][3] + bj1);
                }
                __nv_bfloat16 h0,l0,h1,l1,h2,l2,h3,l3;
                bsplit(v0,h0,l0); bsplit(v1,h1,l1);
                bsplit(v2,h2,l2); bsplit(v3,h3,l3);
                *(uint32_t*)(xhc + (r0e*XST + j)*2)     = pk2(h0,h1);
                *(uint32_t*)(xlc + (r0e*XST + j)*2)     = pk2(l0,l1);
                *(uint32_t*)(xhc + ((r0e+8)*XST + j)*2) = pk2(h2,h3);
                *(uint32_t*)(xlc + ((r0e+8)*XST + j)*2) = pk2(l2,l3);
            }
        }
        if (stage < 2) CP_WAIT(0);
        __syncthreads();       // epilogue writes + next W visible
    }

    // ---------------- final stage ----------------
    if (NODE){
        float val = 0.f;
        int jf = tid & 127, wgn = tid >> 7;
        if (tid < 256){
            const float* Or = O + wgn*KK_*OST + jf;
            const float* mk = smask + wgn*KK_;
            float s = 0.f, msum = 0.f;
            #pragma unroll 6
            for (int r = 0; r < KK_; r++){
                s += mk[r] * Or[r*OST];
                msum += mk[r];
            }
            int node = n0 + wgn;
            val = resid[(size_t)node*HH_ + jf] + (s + b3v[jf]*msum) * kINV_SCALE;
            float s1 = val, s2 = val*val;
            #pragma unroll
            for (int dd = 16; dd > 0; dd >>= 1){
                s1 += __shfl_xor_sync(0xffffffffu, s1, dd);
                s2 += __shfl_xor_sync(0xffffffffu, s2, dd);
            }
            if (lane == 0){ sred[wid] = s1; sred[8 + wid] = s2; }
        }
        __syncthreads();
        if (tid < 256){
            int w0 = wgn*4;
            float t1 = sred[w0]+sred[w0+1]+sred[w0+2]+sred[w0+3];
            float t2 = sred[8+w0]+sred[8+w0+1]+sred[8+w0+2]+sred[8+w0+3];
            float mean = t1*(1.f/128.f);
            float var  = t2*(1.f/128.f) - mean*mean;
            float rs = rsqrtf(var + EPS_);
            int node = n0 + wgn;
            out[(size_t)node*HH_ + jf] = (val - mean)*rs*g[jf] + be[jf];
        }
    } else {
        if (tid < 192){
            int r = tid >> 1, half = tid & 1;
            int nd = n0 + r/KK_, rr = r % KK_;
            size_t rowg = ((size_t)nd*KK_ + rr)*HH_;
            const float* Orow = O + r*OST + half*64;
            const float* hrow = hE + rowg + half*64;
            const float* b3h  = b3v + half*64;
            float s1 = 0.f, s2 = 0.f;
            #pragma unroll 8
            for (int t = 0; t < 64; t++){
                float x = hrow[t] + Orow[t] + b3h[t];
                s1 += x; s2 += x*x;
            }
            s1 += __shfl_xor_sync(0xffffffffu, s1, 1);
            s2 += __shfl_xor_sync(0xffffffffu, s2, 1);
            float mean = s1*(1.f/128.f);
            float var  = s2*(1.f/128.f) - mean*mean;
            float rs = rsqrtf(var + EPS_);
            #pragma unroll 8
            for (int t = 0; t < 64; t++){
                int j = half*64 + t;
                float x = hrow[t] + Orow[t] + b3h[t];
                out[rowg + j] = (x - mean)*rs*g[j] + be[j];
            }
        }
    }
}

// ---------------- FFN + LN2 + mask_V (fp32, validated) ----------------
__global__ void __launch_bounds__(256) ffn_kernel(
    const float* __restrict__ hV1,
    const float* __restrict__ Wi, const float* __restrict__ bi,
    const float* __restrict__ Wo, const float* __restrict__ bo,
    const float* __restrict__ g2, const float* __restrict__ be2,
    const float* __restrict__ maskV,
    float* __restrict__ hV2, float* __restrict__ outV)
{
    __shared__ float sh[8][HH_];
    __shared__ float st[8][FF_ + 4];
    __shared__ float sp[2][8][HH_];
    int tid = threadIdx.x;
    int nb = blockIdx.x * 8;
    for (int idx = tid; idx < 8*HH_; idx += 256)
        sh[idx>>7][idx&127] = hV1[nb*HH_ + idx];
    __syncthreads();
    for (int p = 0; p < 2; p++){
        int jj = p*256 + tid;
        float acc[8];
        float b0 = bi[jj];
        #pragma unroll
        for (int r=0;r<8;r++) acc[r] = b0;
        for (int i=0;i<HH_;i+=4){
            float w0 = Wi[(i+0)*FF_ + jj];
            float w1 = Wi[(i+1)*FF_ + jj];
            float w2 = Wi[(i+2)*FF_ + jj];
            float w3 = Wi[(i+3)*FF_ + jj];
            #pragma unroll
            for (int r=0;r<8;r++){
                float4 h4 = *reinterpret_cast<const float4*>(&sh[r][i]);
                acc[r] = fmaf(h4.x,w0, fmaf(h4.y,w1, fmaf(h4.z,w2, fmaf(h4.w,w3, acc[r]))));
            }
        }
        #pragma unroll
        for (int r=0;r<8;r++) st[r][jj] = gelu_f(acc[r]);
    }
    __syncthreads();
    {
        int o = tid & 127, half = tid >> 7;
        float acc[8];
        #pragma unroll
        for (int r=0;r<8;r++) acc[r]=0.f;
        int i0 = half*256;
        for (int i=i0; i<i0+256; i+=4){
            float w0 = Wo[(i+0)*HH_ + o];
            float w1 = Wo[(i+1)*HH_ + o];
            float w2 = Wo[(i+2)*HH_ + o];
            float w3 = Wo[(i+3)*HH_ + o];
            #pragma unroll
            for (int r=0;r<8;r++){
                float4 t4 = *reinterpret_cast<const float4*>(&st[r][i]);
                acc[r] = fmaf(t4.x,w0, fmaf(t4.y,w1, fmaf(t4.z,w2, fmaf(t4.w,w3, acc[r]))));
            }
        }
        #pragma unroll
        for (int r=0;r<8;r++) sp[half][r][o] = acc[r];
    }
    __syncthreads();
    int r = tid >> 5, lane = tid & 31;
    float v[4]; float s1=0.f, s2=0.f;
    #pragma unroll
    for (int q=0;q<4;q++){
        int oo = lane*4 + q;
        float x = sh[r][oo] + sp[0][r][oo] + sp[1][r][oo] + bo[oo];
        v[q]=x; s1+=x; s2+=x*x;
    }
    #pragma unroll
    for (int dd=16; dd>0; dd>>=1){
        s1 += __shfl_xor_sync(0xffffffffu, s1, dd);
        s2 += __shfl_xor_sync(0xffffffffu, s2, dd);
    }
    float mean = s1*(1.f/128.f);
    float var  = s2*(1.f/128.f) - mean*mean;
    float rs = rsqrtf(var + EPS_);
    float mv = maskV[nb + r];
    #pragma unroll
    for (int q=0;q<4;q++){
        int oo = lane*4 + q;
        float o1 = ((v[q]-mean)*rs*g2[oo] + be2[oo]) * mv;
        hV2 [(nb+r)*HH_ + oo] = o1;
        outV[(nb+r)*HH_ + oo] = o1;
    }
}

// ---------------- launch ----------------
extern "C" void kernel_launch(void* const* d_in, const int* in_sizes, int n_in,
                              void* d_out, int out_size)
{
    (void)in_sizes; (void)n_in; (void)out_size;
    const float* hV    = (const float*)d_in[0];
    const float* hE    = (const float*)d_in[1];
    const int*   Eidx  = (const int*)  d_in[2];
    const float* maskV = (const float*)d_in[3];
    const float* maskA = (const float*)d_in[4];
    const float* W1  = (const float*)d_in[5];
    const float* b1  = (const float*)d_in[6];
    const float* W2  = (const float*)d_in[7];
    const float* b2  = (const float*)d_in[8];
    const float* W3  = (const float*)d_in[9];
    const float* b3  = (const float*)d_in[10];
    const float* W11 = (const float*)d_in[11];
    const float* b11 = (const float*)d_in[12];
    const float* W12 = (const float*)d_in[13];
    const float* b12 = (const float*)d_in[14];
    const float* W13 = (const float*)d_in[15];
    const float* b13 = (const float*)d_in[16];
    const float* Wi  = (const float*)d_in[17];
    const float* bi  = (const float*)d_in[18];
    const float* Wo  = (const float*)d_in[19];
    const float* bo  = (const float*)d_in[20];
    const float* g1  = (const float*)d_in[21];
    const float* be1 = (const float*)d_in[22];
    const float* g2  = (const float*)d_in[23];
    const float* be2 = (const float*)d_in[24];
    const float* g3  = (const float*)d_in[25];
    const float* be3 = (const float*)d_in[26];

    float* outV = (float*)d_out;
    float* outE = outV + (size_t)NB_*HH_;

    float *P, *Q, *hV1, *hV2;
    __nv_bfloat16* WTC;
    cudaGetSymbolAddress((void**)&P,   g_P);
    cudaGetSymbolAddress((void**)&Q,   g_Q);
    cudaGetSymbolAddress((void**)&hV1, g_hV1);
    cudaGetSymbolAddress((void**)&hV2, g_hV2);
    cudaGetSymbolAddress((void**)&WTC, g_WTC);

    cudaFuncSetAttribute(edge_mma_kernel<true>,
                         cudaFuncAttributeMaxDynamicSharedMemorySize, SMEM_BYTES);
    cudaFuncSetAttribute(edge_mma_kernel<false>,
                         cudaFuncAttributeMaxDynamicSharedMemorySize, SMEM_BYTES);

    // weight images (Wt[n][k], bf16 hi/lo, smem-layout-identical)
    wt_prep_kernel<<<64, 256>>>(W1 + HH_*HH_,  WTC + 0*IMG_);
    wt_prep_kernel<<<64, 256>>>(W2,            WTC + 1*IMG_);
    wt_prep_kernel<<<64, 256>>>(W3,            WTC + 2*IMG_);
    wt_prep_kernel<<<64, 256>>>(W11 + HH_*HH_, WTC + 3*IMG_);
    wt_prep_kernel<<<64, 256>>>(W12,           WTC + 4*IMG_);
    wt_prep_kernel<<<64, 256>>>(W13,           WTC + 5*IMG_);

    // --- node update ---
    prep_pq_kernel<<<NB_/8, 256>>>(hV, W1, b1, P, Q);
    edge_mma_kernel<true><<<NB_/2, 384, SMEM_BYTES>>>(
        hE, Eidx, maskA, P, Q, WTC, b2, b3, hV, g1, be1, hV1);
    ffn_kernel<<<NB_/8, 256>>>(hV1, Wi, bi, Wo, bo, g2, be2, maskV, hV2, outV);
    // --- edge update ---
    prep_pq_kernel<<<NB_/8, 256>>>(hV2, W11, b11, P, Q);
    edge_mma_kernel<false><<<NB_/2, 384, SMEM_BYTES>>>(
        hE, Eidx, nullptr, P, Q, WTC + 3*IMG_, b12, b13, nullptr, g3, be3, outE);
}